// round 16
// baseline (speedup 1.0000x reference)
#include <cuda_runtime.h>
#include <cuda_bf16.h>
#include <cuda_fp16.h>
#include <cstdint>

// ---------------------------------------------------------------------------
// RecurrentRetention: B=16, T=2048, D=256, gamma=0.9  — SINGLE mega-kernel.
//   Stage layout by blockIdx (FIFO dispatch => waiters only wait on lower bids):
//     [0,256)     Wq^T -> fp16
//     [256,512)   Wk^T -> fp16 hi/lo
//     [512,544)   wvsum                         -> flag g_c_wv
//     [544,2592)  y[t] (+ x->fp16)              -> flag g_c_y
//     [2592,2720) cgemm c = y @ Wk (fp16 2-pass), waits g_c_y   -> g_c_c
//     [2720,2976) scanA (waits g_c_c) + all-resident barrier + scanBC -> g_c_S
//     [2976,3488) qgemm mainloop (waits g_c_y only!), epilogue waits g_c_S
//   qgemm's MMA work overlaps cgemm+scan completely; only the epilogue
//   scramble-scale needs S. All counters reset by the global last exiter
//   (graph-replay safe). Spin caps degrade to wrong-answer, never hang.
// Error budget: qgemm fp16 1-pass ~2.9e-4 + cgemm fp16 2-pass ~1.9e-4
//   (independent) -> ~3.3e-4 measured in R15; tol 1e-3.
// ---------------------------------------------------------------------------

#define Bsz 16
#define T   2048
#define D   256
#define LTILE 8
#define NTILE (T / LTILE)             // 256
#define GL 0.43046721f                // 0.9^8
#define ROWB 80

#define BID_WV   512
#define BID_Y    544
#define BID_CG   2592
#define BID_SC   2720
#define BID_QG   2976
#define NCTA_TOT 3488

__device__ float g_wvsum[D];
__device__ float g_c[T * D];
__device__ float g_S[T * D];
__device__ float g_carry[NTILE * D];
__device__ __half g_xh[Bsz * T * D];  // x as fp16
__device__ __half g_yh[T * D];        // y as fp16
__device__ __half g_wqh[D * D];       // Wq^T fp16, [n][k]
__device__ __half g_wkh[D * D];       // Wk^T fp16 hi, [n][k]
__device__ __half g_wkl[D * D];       // Wk^T fp16 lo

// epoch counters (zero-init; reset by global last exiter)
__device__ unsigned g_c_wv, g_c_y, g_c_c, g_c_sA, g_c_S, g_c_exit;

__device__ __forceinline__ uint32_t smem_u32(const void* p) {
    uint32_t a;
    asm("{ .reg .u64 t; cvta.to.shared.u64 t, %1; cvt.u32.u64 %0, t; }" : "=r"(a) : "l"(p));
    return a;
}
__device__ __forceinline__ unsigned ldacq(unsigned* p) {
    unsigned v;
    asm volatile("ld.acquire.gpu.u32 %0, [%1];" : "=r"(v) : "l"(p) : "memory");
    return v;
}
__device__ __forceinline__ void wait_ge(unsigned* c, unsigned tgt) {
    if (threadIdx.x == 0) {
        long long spins = 0;
        while (ldacq(c) < tgt) {
            __nanosleep(64);
            if (++spins > 100000000LL) break;   // failsafe: wrong-answer > hang
        }
    }
    __syncthreads();
}
__device__ __forceinline__ void arrive(unsigned* c) {
    __syncthreads();
    __threadfence();
    if (threadIdx.x == 0) atomicAdd(c, 1);
}
__device__ __forceinline__ void ldm_x4(uint32_t* r, uint32_t addr) {
    asm volatile("ldmatrix.sync.aligned.m8n8.x4.shared.b16 {%0,%1,%2,%3}, [%4];"
        : "=r"(r[0]), "=r"(r[1]), "=r"(r[2]), "=r"(r[3]) : "r"(addr));
}
__device__ __forceinline__ void ldm_x2(uint32_t* r, uint32_t addr) {
    asm volatile("ldmatrix.sync.aligned.m8n8.x2.shared.b16 {%0,%1}, [%2];"
        : "=r"(r[0]), "=r"(r[1]) : "r"(addr));
}
__device__ __forceinline__ void mma_fp16(float* c, const uint32_t* a, const uint32_t* b) {
    asm volatile(
        "mma.sync.aligned.m16n8k16.row.col.f32.f16.f16.f32 "
        "{%0,%1,%2,%3}, {%4,%5,%6,%7}, {%8,%9}, {%0,%1,%2,%3};"
        : "+f"(c[0]), "+f"(c[1]), "+f"(c[2]), "+f"(c[3])
        : "r"(a[0]), "r"(a[1]), "r"(a[2]), "r"(a[3]), "r"(b[0]), "r"(b[1]));
}

// unified smem pool (qgemm's 2x(A+B) stages are the max: 40960 bytes)
#define SMEM_BYTES (4 * 128 * ROWB)

__global__ void __launch_bounds__(256, 2)
mega_kernel(const float* __restrict__ x, const float* __restrict__ Wq,
            const float* __restrict__ Wk, const float* __restrict__ Wv,
            float* __restrict__ out) {
    __shared__ char sm[SMEM_BYTES];
    int bid = blockIdx.x, tid = threadIdx.x;

    if (bid < 256) {                        // ---- Wq^T -> fp16 ----
        g_wqh[tid * D + bid] = __float2half_rn(Wq[bid * D + tid]);
    } else if (bid < BID_WV) {              // ---- Wk^T -> fp16 hi/lo ----
        int k = bid - 256;
        float w = Wk[k * D + tid];
        __half h = __float2half_rn(w);
        g_wkh[tid * D + k] = h;
        g_wkl[tid * D + k] = __float2half_rn(w - __half2float(h));
    } else if (bid < BID_Y) {               // ---- wvsum ----
        int row  = (bid - BID_WV) * 8 + (tid >> 5);
        int lane = tid & 31;
        float p = 0.f;
        #pragma unroll
        for (int j = lane; j < D; j += 32) p += Wv[row * D + j];
        #pragma unroll
        for (int off = 16; off; off >>= 1) p += __shfl_xor_sync(0xffffffffu, p, off);
        if (lane == 0) g_wvsum[row] = p;
        arrive(&g_c_wv);
    } else if (bid < BID_CG) {              // ---- y (one t per CTA) ----
        float (*xs)[D] = (float(*)[D])sm;                   // 16KB
        float* vs = (float*)(sm + Bsz * D * 4);             // 64B
        float* wv = (float*)(sm + Bsz * D * 4 + 64);        // 1KB
        int t = bid - BID_Y;
        int e = tid;

        wait_ge(&g_c_wv, 32);
        wv[e] = g_wvsum[e];
        #pragma unroll
        for (int b = 0; b < Bsz; ++b) {
            size_t idx = ((size_t)b * T + t) * D + e;
            float v = x[idx];
            xs[b][e] = v;
            g_xh[idx] = __float2half_rn(v);
        }
        __syncthreads();

        int warp = e >> 5, lane = e & 31;
        #pragma unroll
        for (int rep = 0; rep < 2; ++rep) {
            int b = warp * 2 + rep;
            float p = 0.f;
            #pragma unroll
            for (int k = lane; k < D; k += 32) p += xs[b][k] * wv[k];
            #pragma unroll
            for (int off = 16; off; off >>= 1) p += __shfl_xor_sync(0xffffffffu, p, off);
            if (lane == 0) vs[b] = p;
        }
        __syncthreads();

        float acc = 0.f;
        #pragma unroll
        for (int b = 0; b < Bsz; ++b) acc += vs[b] * xs[b][e];
        g_yh[t * D + e] = __float2half_rn(acc);
        arrive(&g_c_y);
    } else if (bid < BID_SC) {              // ---- cgemm: c = y @ Wk^T ----
        char* sA  = sm;                                     // 32*ROWB
        char* sBh = sm + 32 * ROWB;
        char* sBl = sm + 32 * ROWB + 128 * ROWB;

        int cb = bid - BID_CG;
        int wid = tid >> 5, lane = tid & 31;
        int m0 = (cb & 63) * 32, n0 = (cb >> 6) * 128;
        int mwarp = (wid & 1) * 16, nwarp = (wid >> 1) * 32;

        uint32_t uA = smem_u32(sA);
        uint32_t uBh = smem_u32(sBh), uBl = smem_u32(sBl);

        wait_ge(&g_c_y, T);

        float acc[4][4] = {};
        int arow = lane & 15, ao16 = (lane >> 4) * 16;
        int brow = lane & 7,  bo16 = ((lane >> 3) & 1) * 16;

        for (int kc = 0; kc < 8; ++kc) {
            __syncthreads();
            if (tid < 128) {                 // A: 32 rows x 32 k
                int r = tid >> 2, c16 = tid & 3;
                size_t goff = (size_t)(m0 + r) * 256 + kc * 32 + c16 * 8;
                *(uint4*)(sA + r * ROWB + c16 * 16) = *(const uint4*)(g_yh + goff);
            }
            #pragma unroll
            for (int j = 0; j < 2; ++j) {    // B hi/lo: 128 rows x 32 k
                int i = tid + j * 256;
                int r = i >> 2, c16 = i & 3;
                size_t goff = (size_t)(n0 + r) * 256 + kc * 32 + c16 * 8;
                uint32_t so = r * ROWB + c16 * 16;
                *(uint4*)(sBh + so) = *(const uint4*)(g_wkh + goff);
                *(uint4*)(sBl + so) = *(const uint4*)(g_wkl + goff);
            }
            __syncthreads();

            #pragma unroll
            for (int kk = 0; kk < 2; ++kk) {
                uint32_t af[4], bfh[4][2], bfl[4][2];
                ldm_x4(af, uA + (mwarp + arow) * ROWB + kk * 32 + ao16);
                #pragma unroll
                for (int nf = 0; nf < 4; ++nf) {
                    ldm_x2(bfh[nf], uBh + (nwarp + nf * 8 + brow) * ROWB + kk * 32 + bo16);
                    ldm_x2(bfl[nf], uBl + (nwarp + nf * 8 + brow) * ROWB + kk * 32 + bo16);
                }
                #pragma unroll
                for (int nf = 0; nf < 4; ++nf) {
                    mma_fp16(acc[nf], af, bfh[nf]);
                    mma_fp16(acc[nf], af, bfl[nf]);
                }
            }
        }

        int tq = lane >> 2, tr = (lane & 3) * 2;
        #pragma unroll
        for (int half = 0; half < 2; ++half) {
            int m = m0 + mwarp + tq + half * 8;
            size_t obase = (size_t)m * 256;
            #pragma unroll
            for (int nf = 0; nf < 4; ++nf) {
                int n = n0 + nwarp + nf * 8 + tr;
                float2 v;
                v.x = acc[nf][half * 2 + 0];
                v.y = acc[nf][half * 2 + 1];
                *(float2*)(g_c + obase + n) = v;
            }
        }
        arrive(&g_c_c);
    } else if (bid < BID_QG) {              // ---- scan tile ----
        int g = bid - BID_SC;               // 0..255
        int d = tid;
        int t0 = g * LTILE;

        wait_ge(&g_c_c, 128);
        float s = 0.f;
        #pragma unroll
        for (int i = 0; i < LTILE; ++i) {
            int t = t0 + i;
            float cv = (t == 0) ? 0.f : g_c[t * D + d];
            s = 0.9f * s + cv;
            g_S[t * D + d] = s;
        }
        g_carry[g * D + d] = s;

        arrive(&g_c_sA);
        wait_ge(&g_c_sA, 256);              // all-resident: 256 <= 296 slots

        if (g > 0) {
            float carry = 0.f;
            for (int j = 0; j < g; ++j)
                carry = fmaf(GL, carry, g_carry[j * D + d]);
            float p = 0.9f;
            #pragma unroll
            for (int i = 0; i < LTILE; ++i) {
                g_S[(t0 + i) * D + d] += p * carry;
                p *= 0.9f;
            }
        } else {
            g_S[d] = g_S[D + d];            // S[0] = r[1]
        }
        arrive(&g_c_S);
    } else {                                // ---- qgemm 128x128 tile ----
        char (*sA)[128 * ROWB] = (char(*)[128 * ROWB])sm;
        char (*sB)[128 * ROWB] = (char(*)[128 * ROWB])(sm + 2 * 128 * ROWB);

        int qb = bid - BID_QG;              // 0..511
        int wid = tid >> 5, lane = tid & 31;
        int m0 = (qb & 255) * 128, n0 = (qb >> 8) * 128;
        int mwarp = (wid & 1) * 64, nwarp = (wid >> 1) * 32;

        uint32_t uA0 = smem_u32(sA[0]), uA1 = smem_u32(sA[1]);
        uint32_t uB0 = smem_u32(sB[0]), uB1 = smem_u32(sB[1]);

        float acc[4][4][4] = {};
        int arow = lane & 15, ao16 = (lane >> 4) * 16;
        int brow = lane & 7,  bo16 = ((lane >> 3) & 1) * 16;

        int r0 = tid >> 2, c0 = (tid & 3);
        int r1 = (tid + 256) >> 2, c1 = ((tid + 256) & 3);
        uint32_t so0 = r0 * ROWB + c0 * 16, so1 = r1 * ROWB + c1 * 16;

        wait_ge(&g_c_y, T);                 // xh ready (mainloop needs no S!)

        uint4 ra0, ra1, rb0, rb1;
        auto ldg = [&](int kc) {
            ra0 = *(const uint4*)(g_xh + (size_t)(m0 + r0) * 256 + kc * 32 + c0 * 8);
            ra1 = *(const uint4*)(g_xh + (size_t)(m0 + r1) * 256 + kc * 32 + c1 * 8);
            rb0 = *(const uint4*)(g_wqh + (size_t)(n0 + r0) * 256 + kc * 32 + c0 * 8);
            rb1 = *(const uint4*)(g_wqh + (size_t)(n0 + r1) * 256 + kc * 32 + c1 * 8);
        };
        auto sts = [&](int st) {
            *(uint4*)(sA[st] + so0) = ra0;
            *(uint4*)(sA[st] + so1) = ra1;
            *(uint4*)(sB[st] + so0) = rb0;
            *(uint4*)(sB[st] + so1) = rb1;
        };

        ldg(0);
        sts(0);

        for (int kc = 0; kc < 8; ++kc) {
            __syncthreads();
            if (kc < 7) ldg(kc + 1);
            uint32_t uAh = (kc & 1) ? uA1 : uA0;
            uint32_t uBh = (kc & 1) ? uB1 : uB0;

            #pragma unroll
            for (int kk = 0; kk < 2; ++kk) {
                uint32_t af[4][4], bf[4][2];
                #pragma unroll
                for (int mf = 0; mf < 4; ++mf)
                    ldm_x4(af[mf], uAh + (mwarp + mf * 16 + arow) * ROWB + kk * 32 + ao16);
                #pragma unroll
                for (int nf = 0; nf < 4; ++nf)
                    ldm_x2(bf[nf], uBh + (nwarp + nf * 8 + brow) * ROWB + kk * 32 + bo16);
                #pragma unroll
                for (int mf = 0; mf < 4; ++mf)
                    #pragma unroll
                    for (int nf = 0; nf < 4; ++nf)
                        mma_fp16(acc[mf][nf], af[mf], bf[nf]);
            }
            __syncthreads();
            if (kc < 7) sts((kc + 1) & 1);
        }

        wait_ge(&g_c_S, 256);               // S ready only needed NOW

        int tq = lane >> 2, tr = (lane & 3) * 2;
        #pragma unroll
        for (int mf = 0; mf < 4; ++mf) {
            #pragma unroll
            for (int half = 0; half < 2; ++half) {
                int m = m0 + mwarp + mf * 16 + tq + half * 8;
                size_t obase = (size_t)m * 256;
                int q = m & (T - 1);
                int qh = q >> 8, qc = q & 255;
                #pragma unroll
                for (int nf = 0; nf < 4; ++nf) {
                    int n = n0 + nwarp + nf * 8 + tr;
                    float s0 = g_S[(((n + 0) << 3) + qh) * 256 + qc];
                    float s1 = g_S[(((n + 1) << 3) + qh) * 256 + qc];
                    float2 v;
                    v.x = acc[mf][nf][half * 2 + 0] * s0;
                    v.y = acc[mf][nf][half * 2 + 1] * s1;
                    *(float2*)(out + obase + n) = v;
                }
            }
        }
    }

    // ---- global exit: last CTA resets all counters (graph-replay safe) ----
    __syncthreads();
    if (threadIdx.x == 0) {
        __threadfence();
        unsigned v = atomicAdd(&g_c_exit, 1);
        if (v == (unsigned)(NCTA_TOT - 1)) {
            g_c_wv = 0; g_c_y = 0; g_c_c = 0; g_c_sA = 0; g_c_S = 0;
            __threadfence();
            atomicExch(&g_c_exit, 0);
        }
    }
}

// ======================= launch ============================================
extern "C" void kernel_launch(void* const* d_in, const int* in_sizes, int n_in,
                              void* d_out, int out_size) {
    const float* x  = (const float*)d_in[0];
    const float* Wq = (const float*)d_in[1];
    const float* Wk = (const float*)d_in[2];
    const float* Wv = (const float*)d_in[3];
    float* out = (float*)d_out;

    mega_kernel<<<NCTA_TOT, 256>>>(x, Wq, Wk, Wv, out);
}

// round 17
// speedup vs baseline: 1.2606x; 1.2606x over previous
#include <cuda_runtime.h>
#include <cuda_bf16.h>
#include <cuda_fp16.h>
#include <cstdint>

// ---------------------------------------------------------------------------
// RecurrentRetention: B=16, T=2048, D=256, gamma=0.9
//   vsum[b,t] = x[b,t,:].rowsum(Wv);  y[t,e] = sum_b vsum[b,t]*x[b,t,e]
//   c = y @ Wk;  r[t] = 0.9 r[t-1] + c[t] (exact 2-phase scan) -> S
//   out[b,q,p] = S[8p+(q>>8), q&255] * (x @ Wq)[b,q,p]
// Measured-best multi-kernel pipeline (R14 skeleton) with cgemm switched to
// fp16 2-pass (A=y fp16, B=Wk fp16 hi/lo) — numeric path validated in R15/16
// at rel_err 3.28e-4 (tol 1e-3).
//   qgemm: fp16 1-pass, pre-split xh, register double-buffer
//   scan:  exact 2-phase scanA + scanBC
// ---------------------------------------------------------------------------

#define Bsz 16
#define T   2048
#define D   256
#define LTILE 8
#define NTILE (T / LTILE)             // 256
#define GL 0.43046721f                // 0.9^8
#define ROWB 80

__device__ float g_wvsum[D];
__device__ float g_c[T * D];
__device__ float g_S[T * D];
__device__ float g_carry[NTILE * D];
__device__ __half g_xh[Bsz * T * D];  // x as fp16
__device__ __half g_yh[T * D];        // y as fp16
__device__ __half g_wqh[D * D];       // Wq^T fp16, [n][k]
__device__ __half g_wkh[D * D];       // Wk^T fp16 hi, [n][k]
__device__ __half g_wkl[D * D];       // Wk^T fp16 lo

__device__ __forceinline__ uint32_t smem_u32(const void* p) {
    uint32_t a;
    asm("{ .reg .u64 t; cvta.to.shared.u64 t, %1; cvt.u32.u64 %0, t; }" : "=r"(a) : "l"(p));
    return a;
}
__device__ __forceinline__ void ldm_x4(uint32_t* r, uint32_t addr) {
    asm volatile("ldmatrix.sync.aligned.m8n8.x4.shared.b16 {%0,%1,%2,%3}, [%4];"
        : "=r"(r[0]), "=r"(r[1]), "=r"(r[2]), "=r"(r[3]) : "r"(addr));
}
__device__ __forceinline__ void ldm_x2(uint32_t* r, uint32_t addr) {
    asm volatile("ldmatrix.sync.aligned.m8n8.x2.shared.b16 {%0,%1}, [%2];"
        : "=r"(r[0]), "=r"(r[1]) : "r"(addr));
}
__device__ __forceinline__ void mma_fp16(float* c, const uint32_t* a, const uint32_t* b) {
    asm volatile(
        "mma.sync.aligned.m16n8k16.row.col.f32.f16.f16.f32 "
        "{%0,%1,%2,%3}, {%4,%5,%6,%7}, {%8,%9}, {%0,%1,%2,%3};"
        : "+f"(c[0]), "+f"(c[1]), "+f"(c[2]), "+f"(c[3])
        : "r"(a[0]), "r"(a[1]), "r"(a[2]), "r"(a[3]), "r"(b[0]), "r"(b[1]));
}

// ======================= prep: wvsum + weight transpose-splits =============
__global__ void prep_kernel(const float* __restrict__ Wq, const float* __restrict__ Wk,
                            const float* __restrict__ Wv) {
    int bx = blockIdx.x, tid = threadIdx.x;
    if (bx < 256) {                       // Wq^T -> fp16
        g_wqh[tid * D + bx] = __float2half_rn(Wq[bx * D + tid]);
    } else if (bx < 512) {                // Wk^T -> fp16 hi/lo
        int k = bx - 256;
        float w = Wk[k * D + tid];
        __half h = __float2half_rn(w);
        g_wkh[tid * D + k] = h;
        g_wkl[tid * D + k] = __float2half_rn(w - __half2float(h));
    } else {                              // wvsum
        int row  = (bx - 512) * 8 + (tid >> 5);
        int lane = tid & 31;
        float p = 0.f;
        #pragma unroll
        for (int j = lane; j < D; j += 32) p += Wv[row * D + j];
        #pragma unroll
        for (int off = 16; off; off >>= 1) p += __shfl_xor_sync(0xffffffffu, p, off);
        if (lane == 0) g_wvsum[row] = p;
    }
}

// ======================= y kernel: y fp16 + x fp16 =========================
__global__ void y_kernel(const float* __restrict__ x) {
    __shared__ float xs[Bsz][D];
    __shared__ float vs[Bsz];
    __shared__ float wv[D];
    int t = blockIdx.x;
    int e = threadIdx.x;

    wv[e] = g_wvsum[e];
    #pragma unroll
    for (int b = 0; b < Bsz; ++b) {
        size_t idx = ((size_t)b * T + t) * D + e;
        float v = x[idx];
        xs[b][e] = v;
        g_xh[idx] = __float2half_rn(v);
    }
    __syncthreads();

    int warp = e >> 5, lane = e & 31;
    #pragma unroll
    for (int rep = 0; rep < 2; ++rep) {
        int b = warp * 2 + rep;
        float p = 0.f;
        #pragma unroll
        for (int k = lane; k < D; k += 32) p += xs[b][k] * wv[k];
        #pragma unroll
        for (int off = 16; off; off >>= 1) p += __shfl_xor_sync(0xffffffffu, p, off);
        if (lane == 0) vs[b] = p;
    }
    __syncthreads();

    float acc = 0.f;
    #pragma unroll
    for (int b = 0; b < Bsz; ++b) acc += vs[b] * xs[b][e];
    g_yh[t * D + e] = __float2half_rn(acc);
}

// ======================= cgemm: fp16 2-pass, CTA 32x128 ====================
// c[m,n] = sum_k y[m,k] * Wk[k,n];  A = yh fp16, B = wkh + wkl (fp16 split)
__global__ void __launch_bounds__(256, 2)
cgemm_mma(const __half* __restrict__ ah,
          const __half* __restrict__ bth, const __half* __restrict__ btl,
          float* __restrict__ C) {
    __shared__ char sA[32 * ROWB];
    __shared__ char sBh[128 * ROWB], sBl[128 * ROWB];

    int tid = threadIdx.x, wid = tid >> 5, lane = tid & 31;
    int m0 = blockIdx.x * 32, n0 = blockIdx.y * 128;
    int mwarp = (wid & 1) * 16, nwarp = (wid >> 1) * 32;

    uint32_t uA = smem_u32(sA);
    uint32_t uBh = smem_u32(sBh), uBl = smem_u32(sBl);

    float acc[4][4] = {};
    int arow = lane & 15, ao16 = (lane >> 4) * 16;
    int brow = lane & 7,  bo16 = ((lane >> 3) & 1) * 16;

    for (int kc = 0; kc < 8; ++kc) {
        __syncthreads();
        if (tid < 128) {                     // A: 32 rows x 32 k
            int r = tid >> 2, c16 = tid & 3;
            size_t goff = (size_t)(m0 + r) * 256 + kc * 32 + c16 * 8;
            *(uint4*)(sA + r * ROWB + c16 * 16) = *(const uint4*)(ah + goff);
        }
        #pragma unroll
        for (int j = 0; j < 2; ++j) {        // B hi/lo: 128 rows x 32 k
            int i = tid + j * 256;
            int r = i >> 2, c16 = i & 3;
            size_t goff = (size_t)(n0 + r) * 256 + kc * 32 + c16 * 8;
            uint32_t so = r * ROWB + c16 * 16;
            *(uint4*)(sBh + so) = *(const uint4*)(bth + goff);
            *(uint4*)(sBl + so) = *(const uint4*)(btl + goff);
        }
        __syncthreads();

        #pragma unroll
        for (int kk = 0; kk < 2; ++kk) {
            uint32_t af[4], bfh[4][2], bfl[4][2];
            ldm_x4(af, uA + (mwarp + arow) * ROWB + kk * 32 + ao16);
            #pragma unroll
            for (int nf = 0; nf < 4; ++nf) {
                ldm_x2(bfh[nf], uBh + (nwarp + nf * 8 + brow) * ROWB + kk * 32 + bo16);
                ldm_x2(bfl[nf], uBl + (nwarp + nf * 8 + brow) * ROWB + kk * 32 + bo16);
            }
            #pragma unroll
            for (int nf = 0; nf < 4; ++nf) {
                mma_fp16(acc[nf], af, bfh[nf]);
                mma_fp16(acc[nf], af, bfl[nf]);
            }
        }
    }

    int tq = lane >> 2, tr = (lane & 3) * 2;
    #pragma unroll
    for (int half = 0; half < 2; ++half) {
        int m = m0 + mwarp + tq + half * 8;
        size_t obase = (size_t)m * 256;
        #pragma unroll
        for (int nf = 0; nf < 4; ++nf) {
            int n = n0 + nwarp + nf * 8 + tr;
            float2 v;
            v.x = acc[nf][half * 2 + 0];
            v.y = acc[nf][half * 2 + 1];
            *(float2*)(C + obase + n) = v;
        }
    }
}

// ======================= qgemm: fp16 1-pass, reg double-buffer =============
__global__ void __launch_bounds__(256, 2)
qgemm_mma(const __half* __restrict__ ah, const __half* __restrict__ bth,
          float* __restrict__ C) {
    __shared__ char sA[2][128 * ROWB];
    __shared__ char sB[2][128 * ROWB];

    int tid = threadIdx.x, wid = tid >> 5, lane = tid & 31;
    int m0 = blockIdx.x * 128, n0 = blockIdx.y * 128;
    int mwarp = (wid & 1) * 64, nwarp = (wid >> 1) * 32;

    uint32_t uA0 = smem_u32(sA[0]), uA1 = smem_u32(sA[1]);
    uint32_t uB0 = smem_u32(sB[0]), uB1 = smem_u32(sB[1]);

    float acc[4][4][4] = {};
    int arow = lane & 15, ao16 = (lane >> 4) * 16;
    int brow = lane & 7,  bo16 = ((lane >> 3) & 1) * 16;

    int r0 = tid >> 2, c0 = (tid & 3);
    int r1 = (tid + 256) >> 2, c1 = ((tid + 256) & 3);
    uint32_t so0 = r0 * ROWB + c0 * 16, so1 = r1 * ROWB + c1 * 16;

    uint4 ra0, ra1, rb0, rb1;
    auto ldg = [&](int kc) {
        ra0 = *(const uint4*)(ah + (size_t)(m0 + r0) * 256 + kc * 32 + c0 * 8);
        ra1 = *(const uint4*)(ah + (size_t)(m0 + r1) * 256 + kc * 32 + c1 * 8);
        rb0 = *(const uint4*)(bth + (size_t)(n0 + r0) * 256 + kc * 32 + c0 * 8);
        rb1 = *(const uint4*)(bth + (size_t)(n0 + r1) * 256 + kc * 32 + c1 * 8);
    };
    auto sts = [&](int st) {
        *(uint4*)(sA[st] + so0) = ra0;
        *(uint4*)(sA[st] + so1) = ra1;
        *(uint4*)(sB[st] + so0) = rb0;
        *(uint4*)(sB[st] + so1) = rb1;
    };

    ldg(0);
    sts(0);

    for (int kc = 0; kc < 8; ++kc) {
        __syncthreads();                     // stage kc&1 populated
        if (kc < 7) ldg(kc + 1);             // LDG latency hides under MMA block
        uint32_t uAh = (kc & 1) ? uA1 : uA0;
        uint32_t uBh = (kc & 1) ? uB1 : uB0;

        #pragma unroll
        for (int kk = 0; kk < 2; ++kk) {
            uint32_t af[4][4], bf[4][2];
            #pragma unroll
            for (int mf = 0; mf < 4; ++mf)
                ldm_x4(af[mf], uAh + (mwarp + mf * 16 + arow) * ROWB + kk * 32 + ao16);
            #pragma unroll
            for (int nf = 0; nf < 4; ++nf)
                ldm_x2(bf[nf], uBh + (nwarp + nf * 8 + brow) * ROWB + kk * 32 + bo16);
            #pragma unroll
            for (int mf = 0; mf < 4; ++mf)
                #pragma unroll
                for (int nf = 0; nf < 4; ++nf)
                    mma_fp16(acc[mf][nf], af[mf], bf[nf]);
        }
        __syncthreads();                     // all reads of this stage done
        if (kc < 7) sts((kc + 1) & 1);
    }

    // ---- epilogue: scramble-scale + float2 stores ----
    int tq = lane >> 2, tr = (lane & 3) * 2;
    #pragma unroll
    for (int mf = 0; mf < 4; ++mf) {
        #pragma unroll
        for (int half = 0; half < 2; ++half) {
            int m = m0 + mwarp + mf * 16 + tq + half * 8;
            size_t obase = (size_t)m * 256;
            int q = m & (T - 1);
            int qh = q >> 8, qc = q & 255;
            #pragma unroll
            for (int nf = 0; nf < 4; ++nf) {
                int n = n0 + nwarp + nf * 8 + tr;
                float s0 = g_S[(((n + 0) << 3) + qh) * 256 + qc];
                float s1 = g_S[(((n + 1) << 3) + qh) * 256 + qc];
                float2 v;
                v.x = acc[mf][nf][half * 2 + 0] * s0;
                v.y = acc[mf][nf][half * 2 + 1] * s1;
                *(float2*)(C + obase + n) = v;
            }
        }
    }
}

// ======================= exact 2-phase scan ================================
__global__ void scanA_kernel() {
    int d = threadIdx.x, g = blockIdx.x;
    int t0 = g * LTILE;
    float s = 0.f;
    #pragma unroll
    for (int i = 0; i < LTILE; ++i) {
        int t = t0 + i;
        float cv = (t == 0) ? 0.f : g_c[t * D + d];
        s = 0.9f * s + cv;
        g_S[t * D + d] = s;
    }
    g_carry[g * D + d] = s;
}
// each CTA g reconstructs its incoming carry from g_carry[0..g-1], then fixes
// up its tile. carry array (256KB) is L2-resident and broadcast across CTAs.
__global__ void scanBC_kernel() {
    int d = threadIdx.x, g = blockIdx.x;
    int t0 = g * LTILE;
    if (g == 0) {
        g_S[d] = g_S[D + d];    // S[0] = r[1]
        return;
    }
    float carry = 0.f;
    for (int j = 0; j < g; ++j)
        carry = fmaf(GL, carry, g_carry[j * D + d]);
    float p = 0.9f;
    #pragma unroll
    for (int i = 0; i < LTILE; ++i) {
        g_S[(t0 + i) * D + d] += p * carry;
        p *= 0.9f;
    }
}

// ======================= launch ============================================
extern "C" void kernel_launch(void* const* d_in, const int* in_sizes, int n_in,
                              void* d_out, int out_size) {
    const float* x  = (const float*)d_in[0];
    const float* Wq = (const float*)d_in[1];
    const float* Wk = (const float*)d_in[2];
    const float* Wv = (const float*)d_in[3];
    float* out = (float*)d_out;

    float* c_p; cudaGetSymbolAddress((void**)&c_p, g_c);
    __half* xh_p;  cudaGetSymbolAddress((void**)&xh_p, g_xh);
    __half* yh_p;  cudaGetSymbolAddress((void**)&yh_p, g_yh);
    __half* wqh_p; cudaGetSymbolAddress((void**)&wqh_p, g_wqh);
    __half* wkh_p; cudaGetSymbolAddress((void**)&wkh_p, g_wkh);
    __half* wkl_p; cudaGetSymbolAddress((void**)&wkl_p, g_wkl);

    prep_kernel<<<544, 256>>>(Wq, Wk, Wv);
    y_kernel<<<T, 256>>>(x);
    {
        dim3 grid(T / 32, 2);                 // c = y @ Wk  (128 CTAs)
        cgemm_mma<<<grid, 256>>>(yh_p, wkh_p, wkl_p, c_p);
    }
    scanA_kernel<<<NTILE, 256>>>();
    scanBC_kernel<<<NTILE, 256>>>();
    {
        dim3 grid((Bsz * T) / 128, 2);        // out = scramble(S) * (x @ Wq)
        qgemm_mma<<<grid, 256>>>(xh_p, wqh_p, out);
    }
}